// round 1
// baseline (speedup 1.0000x reference)
#include <cuda_runtime.h>
#include <math.h>

// Problem constants (fixed shapes per setup_inputs)
#define NMAX 50000
#define GMAX 1000
#define LEAK 0.01f
#define EPS  1e-5f

#define CDIV(a,b) (((a)+(b)-1)/(b))

// ---------------- scratch (static device allocations; no cudaMalloc) ---------
__device__ float g_bufA[NMAX*128];
__device__ float g_bufB[NMAX*128];
__device__ float g_bufC[NMAX*128];
__device__ int   g_indeg[NMAX];
__device__ float g_dinv[NMAX];   // rsqrt(indeg+1)  (GCN norm, self-loop incl.)
__device__ float g_rcnt[NMAX];   // 1/max(indeg,1)  (SAGE mean)
__device__ float g_colsum[128];
__device__ float g_colsq[128];
__device__ float g_scale[128];
__device__ float g_shift[128];
__device__ float g_pool[GMAX*32];

// ---------------- degree / norm --------------------------------------------
__global__ void deg_kernel(const int* __restrict__ dst, int nE) {
    int e = blockIdx.x * blockDim.x + threadIdx.x;
    if (e < nE) atomicAdd(&g_indeg[dst[e]], 1);
}

__global__ void dinv_kernel(int n) {
    int i = blockIdx.x * blockDim.x + threadIdx.x;
    if (i < n) {
        int d = g_indeg[i];
        g_dinv[i] = rsqrtf((float)(d + 1));
        g_rcnt[i] = 1.0f / (float)(d > 0 ? d : 1);
    }
}

// ---------------- dense GEMM: Y[n,M] = X[n,K] @ W[K,M] ----------------------
// blockDim = M threads, each block handles ROWS rows.
template <int K, int M, int ROWS>
__global__ void gemm_kernel(const float* __restrict__ X, const float* __restrict__ W,
                            float* __restrict__ Y, int n) {
    __shared__ float xs[ROWS][K];
    int r0  = blockIdx.x * ROWS;
    int tid = threadIdx.x;
    for (int i = tid; i < ROWS * K; i += M) {
        int r = i / K, k = i % K;
        int row = r0 + r;
        xs[r][k] = (row < n) ? X[row * K + k] : 0.0f;
    }
    __syncthreads();
    float acc[ROWS];
#pragma unroll
    for (int r = 0; r < ROWS; r++) acc[r] = 0.0f;
#pragma unroll 4
    for (int k = 0; k < K; k++) {
        float w = W[k * M + tid];
#pragma unroll
        for (int r = 0; r < ROWS; r++) acc[r] = fmaf(xs[r][k], w, acc[r]);
    }
#pragma unroll
    for (int r = 0; r < ROWS; r++) {
        int row = r0 + r;
        if (row < n) Y[row * M + tid] = acc[r];
    }
}

// SAGE fused GEMM: Y = (AGG .* rcnt) @ Wl + H @ Wr    (n x 64), K=128 each
template <int K, int M, int ROWS>
__global__ void sage_gemm_kernel(const float* __restrict__ H, const float* __restrict__ AGG,
                                 const float* __restrict__ Wl, const float* __restrict__ Wr,
                                 float* __restrict__ Y, int n) {
    __shared__ float hs[ROWS][K];
    __shared__ float as[ROWS][K];
    int r0  = blockIdx.x * ROWS;
    int tid = threadIdx.x;  // blockDim = M
    for (int i = tid; i < ROWS * K; i += M) {
        int r = i / K, k = i % K;
        int row = r0 + r;
        if (row < n) {
            hs[r][k] = H[row * K + k];
            as[r][k] = AGG[row * K + k] * g_rcnt[row];
        } else { hs[r][k] = 0.0f; as[r][k] = 0.0f; }
    }
    __syncthreads();
    float acc[ROWS];
#pragma unroll
    for (int r = 0; r < ROWS; r++) acc[r] = 0.0f;
#pragma unroll 2
    for (int k = 0; k < K; k++) {
        float wl = Wl[k * M + tid];
        float wr = Wr[k * M + tid];
#pragma unroll
        for (int r = 0; r < ROWS; r++) {
            acc[r] = fmaf(as[r][k], wl, acc[r]);
            acc[r] = fmaf(hs[r][k], wr, acc[r]);
        }
    }
#pragma unroll
    for (int r = 0; r < ROWS; r++) {
        int row = r0 + r;
        if (row < n) Y[row * M + tid] = acc[r];
    }
}

// ---------------- aggregation (scatter with vector red) ---------------------
// MODE 0: GCN (norm = dinv[s]*dinv[d], plus self items)  MODE 1: plain sum
template <int F, int MODE>
__global__ void agg_kernel(const float* __restrict__ Hin, float* __restrict__ Hout,
                           const int* __restrict__ src, const int* __restrict__ dst,
                           int nE, int n) {
    const int VPE = F / 4;
    int t = blockIdx.x * blockDim.x + threadIdx.x;
    int item = t / VPE;
    int j    = t % VPE;
    int total = (MODE == 0) ? (nE + n) : nE;
    if (item >= total) return;
    int s, d;
    if (item < nE) { s = src[item]; d = dst[item]; }
    else           { s = d = item - nE; }
    float norm = 1.0f;
    if (MODE == 0) norm = g_dinv[s] * g_dinv[d];
    float4 v = ((const float4*)Hin)[s * VPE + j];
    v.x *= norm; v.y *= norm; v.z *= norm; v.w *= norm;
    float4* p = ((float4*)Hout) + d * VPE + j;
    asm volatile("red.global.add.v4.f32 [%0], {%1,%2,%3,%4};"
                 :: "l"(p), "f"(v.x), "f"(v.y), "f"(v.z), "f"(v.w) : "memory");
}

// ---------------- batch norm -------------------------------------------------
template <int C>
__global__ void bn_stats_kernel(const float* __restrict__ X, long long total) {
    __shared__ float s1[256];
    __shared__ float s2[256];
    int tid = threadIdx.x;  // blockDim = 256, 256 % C == 0
    float sum = 0.0f, sq = 0.0f;
    for (long long i = (long long)blockIdx.x * 256 + tid; i < total;
         i += (long long)gridDim.x * 256) {
        float v = X[i];
        sum += v; sq += v * v;
    }
    s1[tid] = sum; s2[tid] = sq;
    __syncthreads();
    for (int off = 128; off >= C; off >>= 1) {
        if (tid < off) { s1[tid] += s1[tid + off]; s2[tid] += s2[tid + off]; }
        __syncthreads();
    }
    if (tid < C) {
        atomicAdd(&g_colsum[tid], s1[tid]);
        atomicAdd(&g_colsq[tid],  s2[tid]);
    }
}

__global__ void bn_finalize_kernel(const float* __restrict__ gamma,
                                   const float* __restrict__ beta, int C, float invn) {
    int c = threadIdx.x;
    if (c < C) {
        float m   = g_colsum[c] * invn;
        float var = g_colsq[c] * invn - m * m;
        float sc  = gamma[c] * rsqrtf(var + EPS);
        g_scale[c] = sc;
        g_shift[c] = beta[c] - m * sc;
    }
}

template <int C>
__global__ void bn_apply_kernel(const float* __restrict__ X, float* __restrict__ Y,
                                long long total) {
    long long i = (long long)blockIdx.x * blockDim.x + threadIdx.x;
    if (i < total) {
        int c = (int)(i & (C - 1));
        float v = fmaf(X[i], g_scale[c], g_shift[c]);
        Y[i] = (v >= 0.0f) ? v : LEAK * v;
    }
}

// ---------------- pool + link ------------------------------------------------
__global__ void pool_kernel(const float* __restrict__ H, const int* __restrict__ batch,
                            const float* __restrict__ b4, int n) {
    int t = blockIdx.x * blockDim.x + threadIdx.x;
    int node = t / 8, j = t % 8;
    if (node >= n) return;
    int g = batch[node];
    float4 v = ((const float4*)H)[node * 8 + j];
    float4 bb = ((const float4*)b4)[j];
    v.x += bb.x; v.y += bb.y; v.z += bb.z; v.w += bb.w;
    float4* p = ((float4*)g_pool) + g * 8 + j;
    asm volatile("red.global.add.v4.f32 [%0], {%1,%2,%3,%4};"
                 :: "l"(p), "f"(v.x), "f"(v.y), "f"(v.z), "f"(v.w) : "memory");
}

__global__ void link_kernel(const int* __restrict__ li, float* __restrict__ out, int L) {
    int w = (blockIdx.x * blockDim.x + threadIdx.x) / 32;
    int lane = threadIdx.x & 31;
    if (w >= L) return;
    int a = li[w], b = li[L + w];
    float v = g_pool[a * 32 + lane] * g_pool[b * 32 + lane];
#pragma unroll
    for (int off = 16; off > 0; off >>= 1)
        v += __shfl_xor_sync(0xFFFFFFFFu, v, off);
    if (lane == 0) out[w] = 1.0f / (1.0f + expf(-v));
}

// ---------------- launch -----------------------------------------------------
extern "C" void kernel_launch(void* const* d_in, const int* in_sizes, int n_in,
                              void* d_out, int out_size) {
    // Input order: x, edge_index, batch, link_indices, [num_graphs], W1,b1,g1,be1,
    //              Wl2,bl2,Wr2,g2,be2, W3,b3,g3,be3, W4,b4
    int base = 4;
    if (n_in >= 20 && in_sizes[4] == 1) base = 5;  // num_graphs scalar present

    const float* x    = (const float*)d_in[0];
    const int*   ei   = (const int*)d_in[1];
    const int*   batch= (const int*)d_in[2];
    const int*   li   = (const int*)d_in[3];
    const float* W1   = (const float*)d_in[base + 0];
    const float* g1   = (const float*)d_in[base + 2];
    const float* be1  = (const float*)d_in[base + 3];
    const float* Wl2  = (const float*)d_in[base + 4];
    const float* Wr2  = (const float*)d_in[base + 6];
    const float* g2   = (const float*)d_in[base + 7];
    const float* be2  = (const float*)d_in[base + 8];
    const float* W3   = (const float*)d_in[base + 9];
    const float* g3   = (const float*)d_in[base + 11];
    const float* be3  = (const float*)d_in[base + 12];
    const float* W4   = (const float*)d_in[base + 13];
    const float* b4   = (const float*)d_in[base + 14];
    float* out = (float*)d_out;

    const int N = in_sizes[0] / 128;
    const int E = in_sizes[1] / 2;
    const int L = in_sizes[3] / 2;
    const int* src = ei;
    const int* dst = ei + E;
    const float invN = 1.0f / (float)N;

    // scratch pointers
    float *bufA, *bufB, *bufC, *poolp;
    int* indeg;
    float *colsum, *colsq;
    cudaGetSymbolAddress((void**)&bufA,   g_bufA);
    cudaGetSymbolAddress((void**)&bufB,   g_bufB);
    cudaGetSymbolAddress((void**)&bufC,   g_bufC);
    cudaGetSymbolAddress((void**)&indeg,  g_indeg);
    cudaGetSymbolAddress((void**)&poolp,  g_pool);
    cudaGetSymbolAddress((void**)&colsum, g_colsum);
    cudaGetSymbolAddress((void**)&colsq,  g_colsq);

    // ---- degree / norms ----
    cudaMemsetAsync(indeg, 0, N * sizeof(int));
    deg_kernel<<<CDIV(E, 256), 256>>>(dst, E);
    dinv_kernel<<<CDIV(N, 256), 256>>>(N);

    // ---- Layer 1: GCN(128->128) + BN + LReLU  (b1 cancels in BN) ----
    gemm_kernel<128, 128, 8><<<CDIV(N, 8), 128>>>(x, W1, bufA, N);
    cudaMemsetAsync(bufB, 0, (size_t)N * 128 * sizeof(float));
    agg_kernel<128, 0><<<CDIV((E + N) * 32, 256), 256>>>(bufA, bufB, src, dst, E, N);
    cudaMemsetAsync(colsum, 0, 128 * sizeof(float));
    cudaMemsetAsync(colsq,  0, 128 * sizeof(float));
    bn_stats_kernel<128><<<1024, 256>>>(bufB, (long long)N * 128);
    bn_finalize_kernel<<<1, 128>>>(g1, be1, 128, invN);
    bn_apply_kernel<128><<<CDIV((long long)N * 128, 256), 256>>>(bufB, bufA, (long long)N * 128);
    // h1 in bufA (N x 128)

    // ---- Layer 2: SAGE(128->64) + BN + LReLU (bl2 cancels in BN) ----
    cudaMemsetAsync(bufB, 0, (size_t)N * 128 * sizeof(float));
    agg_kernel<128, 1><<<CDIV(E * 32, 256), 256>>>(bufA, bufB, src, dst, E, N);
    sage_gemm_kernel<128, 64, 8><<<CDIV(N, 8), 64>>>(bufA, bufB, Wl2, Wr2, bufC, N);
    cudaMemsetAsync(colsum, 0, 64 * sizeof(float));
    cudaMemsetAsync(colsq,  0, 64 * sizeof(float));
    bn_stats_kernel<64><<<1024, 256>>>(bufC, (long long)N * 64);
    bn_finalize_kernel<<<1, 64>>>(g2, be2, 64, invN);
    bn_apply_kernel<64><<<CDIV((long long)N * 64, 256), 256>>>(bufC, bufC, (long long)N * 64);
    // h2 in bufC (N x 64)

    // ---- Layer 3: GCN(64->32) + BN + LReLU (b3 cancels) ----
    gemm_kernel<64, 32, 8><<<CDIV(N, 8), 32>>>(bufC, W3, bufA, N);
    cudaMemsetAsync(bufB, 0, (size_t)N * 32 * sizeof(float));
    agg_kernel<32, 0><<<CDIV((E + N) * 8, 256), 256>>>(bufA, bufB, src, dst, E, N);
    cudaMemsetAsync(colsum, 0, 32 * sizeof(float));
    cudaMemsetAsync(colsq,  0, 32 * sizeof(float));
    bn_stats_kernel<32><<<1024, 256>>>(bufB, (long long)N * 32);
    bn_finalize_kernel<<<1, 32>>>(g3, be3, 32, invN);
    bn_apply_kernel<32><<<CDIV((long long)N * 32, 256), 256>>>(bufB, bufA, (long long)N * 32);
    // h3 in bufA (N x 32)

    // ---- Layer 4: GCN(32->32), b4 folded into pooling ----
    gemm_kernel<32, 32, 8><<<CDIV(N, 8), 32>>>(bufA, W4, bufC, N);
    cudaMemsetAsync(bufB, 0, (size_t)N * 32 * sizeof(float));
    agg_kernel<32, 0><<<CDIV((E + N) * 8, 256), 256>>>(bufC, bufB, src, dst, E, N);

    // ---- pool + link prediction ----
    cudaMemsetAsync(poolp, 0, (size_t)GMAX * 32 * sizeof(float));
    pool_kernel<<<CDIV(N * 8, 256), 256>>>(bufB, batch, b4, N);
    link_kernel<<<CDIV(L * 32, 256), 256>>>(li, out, L);
}

// round 2
// speedup vs baseline: 1.1192x; 1.1192x over previous
#include <cuda_runtime.h>
#include <math.h>

#define NMAX 50000
#define EMAX 800000
#define GMAX 1000
#define LEAK 0.01f
#define EPS  1e-5f
#define CDIV(a,b) (((a)+(b)-1)/(b))

// ---------------- scratch ----------------------------------------------------
__device__ float g_bufA[NMAX*128];
__device__ float g_bufB[NMAX*128];
__device__ float g_bufC[NMAX*128];
__device__ int   g_indeg[NMAX];
__device__ int   g_off[NMAX+1];
__device__ int   g_cur[NMAX];
__device__ int   g_csr[EMAX];
__device__ float g_dinv[NMAX];   // rsqrt(indeg+1)
__device__ float g_rcnt[NMAX];   // 1/max(indeg,1)
__device__ float g_colsum[128];
__device__ float g_colsq[128];
__device__ float g_scale[128];
__device__ float g_shift[128];
__device__ float g_pool[GMAX*32];

// ---------------- degree / norms / CSR --------------------------------------
__global__ void deg_kernel(const int* __restrict__ dst, int nE) {
    int e = blockIdx.x * blockDim.x + threadIdx.x;
    if (e < nE) atomicAdd(&g_indeg[dst[e]], 1);
}

__global__ void dinv_kernel(int n) {
    int i = blockIdx.x * blockDim.x + threadIdx.x;
    if (i < n) {
        int d = g_indeg[i];
        g_dinv[i] = rsqrtf((float)(d + 1));
        g_rcnt[i] = 1.0f / (float)(d > 0 ? d : 1);
    }
}

// single-block exclusive scan of indeg -> off, cur; writes off[n]
__global__ void scan_kernel(int n) {
    __shared__ int part[1024];
    int tid = threadIdx.x;
    int chunk = CDIV(n, 1024);
    int start = tid * chunk;
    int end   = min(start + chunk, n);
    int s = 0;
    for (int i = start; i < end; i++) s += g_indeg[i];
    part[tid] = s;
    __syncthreads();
    for (int off = 1; off < 1024; off <<= 1) {
        int v = (tid >= off) ? part[tid - off] : 0;
        __syncthreads();
        part[tid] += v;
        __syncthreads();
    }
    int run = (tid > 0) ? part[tid - 1] : 0;
    for (int i = start; i < end; i++) {
        g_off[i] = run;
        g_cur[i] = run;
        run += g_indeg[i];
    }
    if (end == n && start < n) g_off[n] = run;
}

__global__ void fill_csr_kernel(const int* __restrict__ src,
                                const int* __restrict__ dst, int nE) {
    int e = blockIdx.x * blockDim.x + threadIdx.x;
    if (e < nE) {
        int p = atomicAdd(&g_cur[dst[e]], 1);
        g_csr[p] = src[e];
    }
}

// ---------------- GEMM: Y[n,M] = X[n,K] @ W[K,M], epilogue * dinv[row]? -----
// blockDim = 128.  RG = 128/M row-groups of ROWS rows; block covers BR = RG*ROWS rows.
template <int K, int M, int ROWS, int PRESCALE>
__global__ void gemm_kernel(const float* __restrict__ X, const float* __restrict__ W,
                            float* __restrict__ Y, int n) {
    const int RG  = 128 / M;
    const int BR  = RG * ROWS;
    const int PBR = BR + 4;                 // pad (multiple of 4) kills bank conflicts
    __shared__ float xs[K * PBR];
    int tid = threadIdx.x;
    int r0  = blockIdx.x * BR;
    for (int i = tid; i < BR * K; i += 128) {
        int r = i / K, k = i % K;
        int row = r0 + r;
        xs[k * PBR + r] = (row < n) ? X[row * K + k] : 0.0f;
    }
    __syncthreads();
    int col = tid % M;
    int rg  = tid / M;
    float acc[ROWS];
#pragma unroll
    for (int r = 0; r < ROWS; r++) acc[r] = 0.0f;
#pragma unroll 4
    for (int k = 0; k < K; k++) {
        float w = W[k * M + col];
        const float4* xv = (const float4*)&xs[k * PBR + rg * ROWS];
#pragma unroll
        for (int r4 = 0; r4 < ROWS / 4; r4++) {
            float4 xx = xv[r4];
            acc[r4*4+0] = fmaf(xx.x, w, acc[r4*4+0]);
            acc[r4*4+1] = fmaf(xx.y, w, acc[r4*4+1]);
            acc[r4*4+2] = fmaf(xx.z, w, acc[r4*4+2]);
            acc[r4*4+3] = fmaf(xx.w, w, acc[r4*4+3]);
        }
    }
#pragma unroll
    for (int r = 0; r < ROWS; r++) {
        int row = r0 + rg * ROWS + r;
        if (row < n) {
            float v = acc[r];
            if (PRESCALE) v *= g_dinv[row];
            Y[row * M + col] = v;
        }
    }
}

// SAGE fused GEMM: Y = AGG @ Wl + H @ Wr  (K=128, M=64)
template <int K, int M, int ROWS>
__global__ void sage_gemm_kernel(const float* __restrict__ H, const float* __restrict__ AGG,
                                 const float* __restrict__ Wl, const float* __restrict__ Wr,
                                 float* __restrict__ Y, int n) {
    const int RG  = 128 / M;
    const int BR  = RG * ROWS;
    const int PBR = BR + 4;
    __shared__ float hs[K * PBR];
    __shared__ float as[K * PBR];
    int tid = threadIdx.x;
    int r0  = blockIdx.x * BR;
    for (int i = tid; i < BR * K; i += 128) {
        int r = i / K, k = i % K;
        int row = r0 + r;
        hs[k * PBR + r] = (row < n) ? H[row * K + k] : 0.0f;
        as[k * PBR + r] = (row < n) ? AGG[row * K + k] : 0.0f;
    }
    __syncthreads();
    int col = tid % M;
    int rg  = tid / M;
    float acc[ROWS];
#pragma unroll
    for (int r = 0; r < ROWS; r++) acc[r] = 0.0f;
#pragma unroll 2
    for (int k = 0; k < K; k++) {
        float wl = Wl[k * M + col];
        float wr = Wr[k * M + col];
        const float4* hv = (const float4*)&hs[k * PBR + rg * ROWS];
        const float4* av = (const float4*)&as[k * PBR + rg * ROWS];
#pragma unroll
        for (int r4 = 0; r4 < ROWS / 4; r4++) {
            float4 hh = hv[r4];
            float4 aa = av[r4];
            acc[r4*4+0] = fmaf(aa.x, wl, fmaf(hh.x, wr, acc[r4*4+0]));
            acc[r4*4+1] = fmaf(aa.y, wl, fmaf(hh.y, wr, acc[r4*4+1]));
            acc[r4*4+2] = fmaf(aa.z, wl, fmaf(hh.z, wr, acc[r4*4+2]));
            acc[r4*4+3] = fmaf(aa.w, wl, fmaf(hh.w, wr, acc[r4*4+3]));
        }
    }
#pragma unroll
    for (int r = 0; r < ROWS; r++) {
        int row = r0 + rg * ROWS + r;
        if (row < n) Y[row * M + col] = acc[r];
    }
}

// ---------------- CSR gather aggregation ------------------------------------
// F=128. warp per node, lane owns float4 slot.
// MODE 0: GCN — Hin is pre-scaled by dinv[src]; acc init = self; out *= dinv[node]
// MODE 1: SAGE mean — acc init 0; out *= rcnt[node]
template <int MODE>
__global__ void gather128_kernel(const float* __restrict__ Hin, float* __restrict__ Hout,
                                 int n) {
    int warp = (blockIdx.x * blockDim.x + threadIdx.x) >> 5;
    int lane = threadIdx.x & 31;
    if (warp >= n) return;
    int beg = g_off[warp], end = g_off[warp + 1];
    const float4* H4 = (const float4*)Hin;
    float4 acc;
    if (MODE == 0) acc = H4[warp * 32 + lane];
    else           acc = make_float4(0.f, 0.f, 0.f, 0.f);
#pragma unroll 4
    for (int e = beg; e < end; e++) {
        int s = __ldg(&g_csr[e]);
        float4 v = H4[s * 32 + lane];
        acc.x += v.x; acc.y += v.y; acc.z += v.z; acc.w += v.w;
    }
    float sc = (MODE == 0) ? g_dinv[warp] : g_rcnt[warp];
    float4 o = make_float4(acc.x * sc, acc.y * sc, acc.z * sc, acc.w * sc);
    ((float4*)Hout)[warp * 32 + lane] = o;
}

// F=32 GCN gather. warp per node, lane owns one column.
__global__ void gather32_kernel(const float* __restrict__ Hin, float* __restrict__ Hout,
                                int n) {
    int warp = (blockIdx.x * blockDim.x + threadIdx.x) >> 5;
    int lane = threadIdx.x & 31;
    if (warp >= n) return;
    int beg = g_off[warp], end = g_off[warp + 1];
    float acc = Hin[warp * 32 + lane];
#pragma unroll 4
    for (int e = beg; e < end; e++) {
        int s = __ldg(&g_csr[e]);
        acc += Hin[s * 32 + lane];
    }
    Hout[warp * 32 + lane] = acc * g_dinv[warp];
}

// ---------------- batch norm -------------------------------------------------
template <int C>
__global__ void bn_stats_kernel(const float* __restrict__ X, long long total) {
    __shared__ float s1[256];
    __shared__ float s2[256];
    int tid = threadIdx.x;
    float sum = 0.0f, sq = 0.0f;
    for (long long i = (long long)blockIdx.x * 256 + tid; i < total;
         i += (long long)gridDim.x * 256) {
        float v = X[i];
        sum += v; sq += v * v;
    }
    s1[tid] = sum; s2[tid] = sq;
    __syncthreads();
    for (int off = 128; off >= C; off >>= 1) {
        if (tid < off) { s1[tid] += s1[tid + off]; s2[tid] += s2[tid + off]; }
        __syncthreads();
    }
    if (tid < C) {
        atomicAdd(&g_colsum[tid], s1[tid]);
        atomicAdd(&g_colsq[tid],  s2[tid]);
    }
}

__global__ void bn_finalize_kernel(const float* __restrict__ gamma,
                                   const float* __restrict__ beta, int C, float invn) {
    int c = threadIdx.x;
    if (c < C) {
        float m   = g_colsum[c] * invn;
        float var = g_colsq[c] * invn - m * m;
        float sc  = gamma[c] * rsqrtf(var + EPS);
        g_scale[c] = sc;
        g_shift[c] = beta[c] - m * sc;
    }
}

template <int C>
__global__ void bn_apply_kernel(const float* __restrict__ X, float* __restrict__ Y,
                                long long total) {
    long long i = (long long)blockIdx.x * blockDim.x + threadIdx.x;
    if (i < total) {
        int c = (int)(i & (C - 1));
        float v = fmaf(X[i], g_scale[c], g_shift[c]);
        Y[i] = (v >= 0.0f) ? v : LEAK * v;
    }
}

// ---------------- pool + link ------------------------------------------------
__global__ void pool_kernel(const float* __restrict__ H, const int* __restrict__ batch,
                            const float* __restrict__ b4, int n) {
    int t = blockIdx.x * blockDim.x + threadIdx.x;
    int node = t / 8, j = t % 8;
    if (node >= n) return;
    int g = batch[node];
    float4 v = ((const float4*)H)[node * 8 + j];
    float4 bb = ((const float4*)b4)[j];
    v.x += bb.x; v.y += bb.y; v.z += bb.z; v.w += bb.w;
    float4* p = ((float4*)g_pool) + g * 8 + j;
    asm volatile("red.global.add.v4.f32 [%0], {%1,%2,%3,%4};"
                 :: "l"(p), "f"(v.x), "f"(v.y), "f"(v.z), "f"(v.w) : "memory");
}

__global__ void link_kernel(const int* __restrict__ li, float* __restrict__ out, int L) {
    int w = (blockIdx.x * blockDim.x + threadIdx.x) / 32;
    int lane = threadIdx.x & 31;
    if (w >= L) return;
    int a = li[w], b = li[L + w];
    float v = g_pool[a * 32 + lane] * g_pool[b * 32 + lane];
#pragma unroll
    for (int off = 16; off > 0; off >>= 1)
        v += __shfl_xor_sync(0xFFFFFFFFu, v, off);
    if (lane == 0) out[w] = 1.0f / (1.0f + expf(-v));
}

// ---------------- launch -----------------------------------------------------
extern "C" void kernel_launch(void* const* d_in, const int* in_sizes, int n_in,
                              void* d_out, int out_size) {
    int base = 4;
    if (n_in >= 20 && in_sizes[4] == 1) base = 5;

    const float* x    = (const float*)d_in[0];
    const int*   ei   = (const int*)d_in[1];
    const int*   batch= (const int*)d_in[2];
    const int*   li   = (const int*)d_in[3];
    const float* W1   = (const float*)d_in[base + 0];
    const float* g1   = (const float*)d_in[base + 2];
    const float* be1  = (const float*)d_in[base + 3];
    const float* Wl2  = (const float*)d_in[base + 4];
    const float* Wr2  = (const float*)d_in[base + 6];
    const float* g2   = (const float*)d_in[base + 7];
    const float* be2  = (const float*)d_in[base + 8];
    const float* W3   = (const float*)d_in[base + 9];
    const float* g3   = (const float*)d_in[base + 11];
    const float* be3  = (const float*)d_in[base + 12];
    const float* W4   = (const float*)d_in[base + 13];
    const float* b4   = (const float*)d_in[base + 14];
    float* out = (float*)d_out;

    const int N = in_sizes[0] / 128;
    const int E = in_sizes[1] / 2;
    const int L = in_sizes[3] / 2;
    const int* src = ei;
    const int* dst = ei + E;
    const float invN = 1.0f / (float)N;

    float *bufA, *bufB, *bufC, *poolp, *colsum, *colsq;
    int* indeg;
    cudaGetSymbolAddress((void**)&bufA,   g_bufA);
    cudaGetSymbolAddress((void**)&bufB,   g_bufB);
    cudaGetSymbolAddress((void**)&bufC,   g_bufC);
    cudaGetSymbolAddress((void**)&indeg,  g_indeg);
    cudaGetSymbolAddress((void**)&poolp,  g_pool);
    cudaGetSymbolAddress((void**)&colsum, g_colsum);
    cudaGetSymbolAddress((void**)&colsq,  g_colsq);

    // ---- degrees, norms, CSR (by dst) ----
    cudaMemsetAsync(indeg, 0, N * sizeof(int));
    deg_kernel<<<CDIV(E, 256), 256>>>(dst, E);
    dinv_kernel<<<CDIV(N, 256), 256>>>(N);
    scan_kernel<<<1, 1024>>>(N);
    fill_csr_kernel<<<CDIV(E, 256), 256>>>(src, dst, E);

    // ---- Layer 1: GCN(128->128) + BN + LReLU  (b1 cancels in BN) ----
    gemm_kernel<128, 128, 8, 1><<<CDIV(N, 8), 128>>>(x, W1, bufA, N);   // pre-scaled by dinv
    gather128_kernel<0><<<CDIV(N * 32, 256), 256>>>(bufA, bufB, N);
    cudaMemsetAsync(colsum, 0, 128 * sizeof(float));
    cudaMemsetAsync(colsq,  0, 128 * sizeof(float));
    bn_stats_kernel<128><<<1024, 256>>>(bufB, (long long)N * 128);
    bn_finalize_kernel<<<1, 128>>>(g1, be1, 128, invN);
    bn_apply_kernel<128><<<CDIV((long long)N * 128, 256), 256>>>(bufB, bufA, (long long)N * 128);
    // h1 in bufA (N x 128)

    // ---- Layer 2: SAGE(128->64) + BN + LReLU (bl2 cancels) ----
    gather128_kernel<1><<<CDIV(N * 32, 256), 256>>>(bufA, bufB, N);     // mean agg
    sage_gemm_kernel<128, 64, 8><<<CDIV(N, 16), 128>>>(bufA, bufB, Wl2, Wr2, bufC, N);
    cudaMemsetAsync(colsum, 0, 64 * sizeof(float));
    cudaMemsetAsync(colsq,  0, 64 * sizeof(float));
    bn_stats_kernel<64><<<1024, 256>>>(bufC, (long long)N * 64);
    bn_finalize_kernel<<<1, 64>>>(g2, be2, 64, invN);
    bn_apply_kernel<64><<<CDIV((long long)N * 64, 256), 256>>>(bufC, bufC, (long long)N * 64);
    // h2 in bufC (N x 64)

    // ---- Layer 3: GCN(64->32) + BN + LReLU ----
    gemm_kernel<64, 32, 8, 1><<<CDIV(N, 32), 128>>>(bufC, W3, bufA, N);
    gather32_kernel<<<CDIV(N * 32, 256), 256>>>(bufA, bufB, N);
    cudaMemsetAsync(colsum, 0, 32 * sizeof(float));
    cudaMemsetAsync(colsq,  0, 32 * sizeof(float));
    bn_stats_kernel<32><<<1024, 256>>>(bufB, (long long)N * 32);
    bn_finalize_kernel<<<1, 32>>>(g3, be3, 32, invN);
    bn_apply_kernel<32><<<CDIV((long long)N * 32, 256), 256>>>(bufB, bufA, (long long)N * 32);
    // h3 in bufA (N x 32)

    // ---- Layer 4: GCN(32->32), b4 folded into pooling ----
    gemm_kernel<32, 32, 8, 1><<<CDIV(N, 32), 128>>>(bufA, W4, bufC, N);
    gather32_kernel<<<CDIV(N * 32, 256), 256>>>(bufC, bufB, N);

    // ---- pool + link prediction ----
    cudaMemsetAsync(poolp, 0, (size_t)GMAX * 32 * sizeof(float));
    pool_kernel<<<CDIV(N * 8, 256), 256>>>(bufB, batch, b4, N);
    link_kernel<<<CDIV(L * 32, 256), 256>>>(li, out, L);
}